// round 2
// baseline (speedup 1.0000x reference)
#include <cuda_runtime.h>

// GRU seq2seq forecaster — persistent fp32 kernel, 8 threads per batch row.
// B=4096, T_IN=168, C=32, H=64, T_OUT=24.

#define B_    4096
#define TIN   168
#define C_    32
#define H_    64
#define TOUT  24
#define RPC   28              // rows per CTA
#define TPC   (RPC * 8)       // 224 threads
#define NCTA  ((B_ + RPC - 1) / RPC)   // 147
#define WIH_S 36              // padded stride for Wih rows (32 -> 36 floats)
#define WHH_S 68              // padded stride for Whh rows (64 -> 68 floats)

// shared layout (floats)
#define SM_FLOATS (2*(192*WIH_S + 192*WHH_S) + 8*64 + 32*WHH_S + 32 + RPC*WHH_S + RPC*WIH_S)
#define SM_BYTES  (SM_FLOATS * 4)

__device__ __forceinline__ float fsig(float a) {
    // sigmoid via fast exp: max rel err ~1e-6; saturates cleanly (exp->inf/0)
    return __fdividef(1.0f, 1.0f + __expf(-a));
}
__device__ __forceinline__ float ftanh(float a) {
    // tanh(a) = 1 - 2/(exp(2a)+1); saturates cleanly for |a| large
    float e = __expf(2.0f * a);
    return 1.0f - __fdividef(2.0f, e + 1.0f);
}

// One GRU step for this thread's 8 hidden units. xv/hv are register copies of
// the full input (32) and hidden (64) vectors for this row. Writes new h
// values into sHrow[j] (4B scattered, disjoint across the row's 8 threads).
__device__ __forceinline__ void gru_step(
    const float* __restrict__ sWih, const float* __restrict__ sWhh,
    const float* __restrict__ sbr,  const float* __restrict__ sbz,
    const float* __restrict__ sbni, const float* __restrict__ sbnh,
    const float xv[C_], const float hv[H_], float* __restrict__ sHrow, int js)
{
#pragma unroll 1
    for (int i = 0; i < 8; i++) {
        const int j = js + 8 * i;          // interleaved ownership -> conflict-free LDS
        float ar  = sbr[j];                // r gate pre-act (bih_r + bhh_r folded)
        float az  = sbz[j];                // z gate pre-act
        float ani = sbni[j];               // n gate, input part (bih_n)
        float ahn = sbnh[j];               // n gate, hidden part (bhh_n)

        const float4* wr = reinterpret_cast<const float4*>(sWih + (size_t)(      j) * WIH_S);
        const float4* wz = reinterpret_cast<const float4*>(sWih + (size_t)( 64 + j) * WIH_S);
        const float4* wn = reinterpret_cast<const float4*>(sWih + (size_t)(128 + j) * WIH_S);
#pragma unroll
        for (int q = 0; q < C_ / 4; q++) {
            float4 a = wr[q], b = wz[q], c = wn[q];
            ar  = fmaf(a.x, xv[4*q+0], ar);  ar  = fmaf(a.y, xv[4*q+1], ar);
            ar  = fmaf(a.z, xv[4*q+2], ar);  ar  = fmaf(a.w, xv[4*q+3], ar);
            az  = fmaf(b.x, xv[4*q+0], az);  az  = fmaf(b.y, xv[4*q+1], az);
            az  = fmaf(b.z, xv[4*q+2], az);  az  = fmaf(b.w, xv[4*q+3], az);
            ani = fmaf(c.x, xv[4*q+0], ani); ani = fmaf(c.y, xv[4*q+1], ani);
            ani = fmaf(c.z, xv[4*q+2], ani); ani = fmaf(c.w, xv[4*q+3], ani);
        }
        const float4* ur = reinterpret_cast<const float4*>(sWhh + (size_t)(      j) * WHH_S);
        const float4* uz = reinterpret_cast<const float4*>(sWhh + (size_t)( 64 + j) * WHH_S);
        const float4* un = reinterpret_cast<const float4*>(sWhh + (size_t)(128 + j) * WHH_S);
#pragma unroll
        for (int q = 0; q < H_ / 4; q++) {
            float4 a = ur[q], b = uz[q], c = un[q];
            ar  = fmaf(a.x, hv[4*q+0], ar);  ar  = fmaf(a.y, hv[4*q+1], ar);
            ar  = fmaf(a.z, hv[4*q+2], ar);  ar  = fmaf(a.w, hv[4*q+3], ar);
            az  = fmaf(b.x, hv[4*q+0], az);  az  = fmaf(b.y, hv[4*q+1], az);
            az  = fmaf(b.z, hv[4*q+2], az);  az  = fmaf(b.w, hv[4*q+3], az);
            ahn = fmaf(c.x, hv[4*q+0], ahn); ahn = fmaf(c.y, hv[4*q+1], ahn);
            ahn = fmaf(c.z, hv[4*q+2], ahn); ahn = fmaf(c.w, hv[4*q+3], ahn);
        }
        const float r = fsig(ar);
        const float z = fsig(az);
        const float n = ftanh(fmaf(r, ahn, ani));
        const float hold = sHrow[j];       // old h_j still in shared (we only overwrite own j)
        sHrow[j] = (1.0f - z) * n + z * hold;
    }
}

__global__ __launch_bounds__(TPC, 1)
void gru_forecast_kernel(
    const float* __restrict__ x,
    const float* __restrict__ eWih, const float* __restrict__ eWhh,
    const float* __restrict__ eBih, const float* __restrict__ eBhh,
    const float* __restrict__ dWih, const float* __restrict__ dWhh,
    const float* __restrict__ dBih, const float* __restrict__ dBhh,
    const float* __restrict__ pW,   const float* __restrict__ pB,
    float* __restrict__ out)
{
    extern __shared__ float sm[];
    float* sWih_e = sm;
    float* sWhh_e = sWih_e + 192 * WIH_S;
    float* sWih_d = sWhh_e + 192 * WHH_S;
    float* sWhh_d = sWih_d + 192 * WIH_S;
    float* sbr_e  = sWhh_d + 192 * WHH_S;
    float* sbz_e  = sbr_e  + 64;
    float* sbni_e = sbz_e  + 64;
    float* sbnh_e = sbni_e + 64;
    float* sbr_d  = sbnh_e + 64;
    float* sbz_d  = sbr_d  + 64;
    float* sbni_d = sbz_d  + 64;
    float* sbnh_d = sbni_d + 64;
    float* sPW    = sbnh_d + 64;          // 32 * WHH_S
    float* sPb    = sPW   + 32 * WHH_S;   // 32
    float* sH     = sPb   + 32;           // RPC * WHH_S
    float* sPrev  = sH    + RPC * WHH_S;  // RPC * WIH_S

    const int tid = threadIdx.x;

    // ---- stage weights into padded shared (bank-phase friendly strides) ----
    for (int i = tid; i < 192 * 32; i += TPC) {
        const int j = i >> 5, k = i & 31;
        sWih_e[j * WIH_S + k] = eWih[i];
        sWih_d[j * WIH_S + k] = dWih[i];
    }
    for (int i = tid; i < 192 * 64; i += TPC) {
        const int j = i >> 6, k = i & 63;
        sWhh_e[j * WHH_S + k] = eWhh[i];
        sWhh_d[j * WHH_S + k] = dWhh[i];
    }
    for (int j = tid; j < 64; j += TPC) {
        sbr_e[j]  = eBih[j]       + eBhh[j];        // r-gate biases fold
        sbz_e[j]  = eBih[64 + j]  + eBhh[64 + j];   // z-gate biases fold
        sbni_e[j] = eBih[128 + j];
        sbnh_e[j] = eBhh[128 + j];                  // stays inside r*(...) term
        sbr_d[j]  = dBih[j]       + dBhh[j];
        sbz_d[j]  = dBih[64 + j]  + dBhh[64 + j];
        sbni_d[j] = dBih[128 + j];
        sbnh_d[j] = dBhh[128 + j];
    }
    for (int i = tid; i < 32 * 64; i += TPC) {
        const int c = i >> 6, k = i & 63;
        sPW[c * WHH_S + k] = pW[i];
    }
    for (int i = tid; i < 32; i += TPC) sPb[i] = pB[i];
    for (int i = tid; i < RPC * WHH_S; i += TPC) sH[i] = 0.0f;
    __syncthreads();   // only block barrier in the whole kernel

    const int rl = tid >> 3;       // local row 0..27
    const int js = tid & 7;        // j-slot 0..7 within row
    const int growr = blockIdx.x * RPC + rl;
    const bool active = (growr < B_);
    const int row = active ? growr : (B_ - 1);   // clamp; compute is harmless, stores guarded

    const float* xrow = x + (size_t)row * (TIN * C_);
    float* sHrow    = sH    + rl * WHH_S;
    float* sPrevRow = sPrev + rl * WIH_S;

    float hv[H_];
#pragma unroll
    for (int k = 0; k < H_; k++) hv[k] = 0.0f;
    float xv[C_];

    // ---------------- encoder: 168 steps ----------------
    for (int t = 0; t < TIN; t++) {
        const float4* xp = reinterpret_cast<const float4*>(xrow + t * C_);
#pragma unroll
        for (int q = 0; q < C_ / 4; q++) {
            float4 v = xp[q];
            xv[4*q+0] = v.x; xv[4*q+1] = v.y; xv[4*q+2] = v.z; xv[4*q+3] = v.w;
        }
        gru_step(sWih_e, sWhh_e, sbr_e, sbz_e, sbni_e, sbnh_e, xv, hv, sHrow, js);
        __syncwarp();                      // writes to sH visible to row's lanes
#pragma unroll
        for (int q = 0; q < H_ / 4; q++) { // reload full h into registers
            float4 v = *reinterpret_cast<const float4*>(sHrow + 4 * q);
            hv[4*q+0] = v.x; hv[4*q+1] = v.y; hv[4*q+2] = v.z; hv[4*q+3] = v.w;
        }
        __syncwarp();                      // all lanes done reading before next writes
    }

    // decoder start token: prev = x[:, T_IN-1, :]
    {
        const float4* xp = reinterpret_cast<const float4*>(xrow + (TIN - 1) * C_);
        float4 v = xp[js];
        *reinterpret_cast<float4*>(sPrevRow + 4 * js) = v;
        __syncwarp();
    }

    // ---------------- decoder: 24 steps ----------------
    const int c0 = 4 * js;   // this thread's 4 projection outputs
    for (int t = 0; t < TOUT; t++) {
#pragma unroll
        for (int q = 0; q < C_ / 4; q++) {
            float4 v = *reinterpret_cast<const float4*>(sPrevRow + 4 * q);
            xv[4*q+0] = v.x; xv[4*q+1] = v.y; xv[4*q+2] = v.z; xv[4*q+3] = v.w;
        }
        __syncwarp();                      // prev reads done before anyone rewrites sPrev
        gru_step(sWih_d, sWhh_d, sbr_d, sbz_d, sbni_d, sbnh_d, xv, hv, sHrow, js);
        __syncwarp();
#pragma unroll
        for (int q = 0; q < H_ / 4; q++) {
            float4 v = *reinterpret_cast<const float4*>(sHrow + 4 * q);
            hv[4*q+0] = v.x; hv[4*q+1] = v.y; hv[4*q+2] = v.z; hv[4*q+3] = v.w;
        }
        // projection: pred[c0..c0+3] = h @ proj_W^T + b
        float p0 = sPb[c0 + 0], p1 = sPb[c0 + 1], p2 = sPb[c0 + 2], p3 = sPb[c0 + 3];
        const float4* w0 = reinterpret_cast<const float4*>(sPW + (size_t)(c0 + 0) * WHH_S);
        const float4* w1 = reinterpret_cast<const float4*>(sPW + (size_t)(c0 + 1) * WHH_S);
        const float4* w2 = reinterpret_cast<const float4*>(sPW + (size_t)(c0 + 2) * WHH_S);
        const float4* w3 = reinterpret_cast<const float4*>(sPW + (size_t)(c0 + 3) * WHH_S);
#pragma unroll
        for (int q = 0; q < H_ / 4; q++) {
            float4 a = w0[q], b = w1[q], c = w2[q], d = w3[q];
            p0 = fmaf(a.x, hv[4*q+0], p0); p0 = fmaf(a.y, hv[4*q+1], p0);
            p0 = fmaf(a.z, hv[4*q+2], p0); p0 = fmaf(a.w, hv[4*q+3], p0);
            p1 = fmaf(b.x, hv[4*q+0], p1); p1 = fmaf(b.y, hv[4*q+1], p1);
            p1 = fmaf(b.z, hv[4*q+2], p1); p1 = fmaf(b.w, hv[4*q+3], p1);
            p2 = fmaf(c.x, hv[4*q+0], p2); p2 = fmaf(c.y, hv[4*q+1], p2);
            p2 = fmaf(c.z, hv[4*q+2], p2); p2 = fmaf(c.w, hv[4*q+3], p2);
            p3 = fmaf(d.x, hv[4*q+0], p3); p3 = fmaf(d.y, hv[4*q+1], p3);
            p3 = fmaf(d.z, hv[4*q+2], p3); p3 = fmaf(d.w, hv[4*q+3], p3);
        }
        float4 pr = make_float4(p0, p1, p2, p3);
        *reinterpret_cast<float4*>(sPrevRow + c0) = pr;   // becomes next step's input
        if (active) {
            *reinterpret_cast<float4*>(out + ((size_t)row * TOUT + t) * C_ + c0) = pr;
        }
        __syncwarp();
    }
}

extern "C" void kernel_launch(void* const* d_in, const int* in_sizes, int n_in,
                              void* d_out, int out_size)
{
    (void)in_sizes; (void)n_in; (void)out_size;
    const float* x    = (const float*)d_in[0];
    const float* eWih = (const float*)d_in[1];
    const float* eWhh = (const float*)d_in[2];
    const float* eBih = (const float*)d_in[3];
    const float* eBhh = (const float*)d_in[4];
    const float* dWih = (const float*)d_in[5];
    const float* dWhh = (const float*)d_in[6];
    const float* dBih = (const float*)d_in[7];
    const float* dBhh = (const float*)d_in[8];
    const float* pW   = (const float*)d_in[9];
    const float* pB   = (const float*)d_in[10];
    float* out = (float*)d_out;

    cudaFuncSetAttribute(gru_forecast_kernel,
                         cudaFuncAttributeMaxDynamicSharedMemorySize, SM_BYTES);
    gru_forecast_kernel<<<NCTA, TPC, SM_BYTES>>>(
        x, eWih, eWhh, eBih, eBhh, dWih, dWhh, dBih, dBhh, pW, pB, out);
}

// round 3
// speedup vs baseline: 1.0008x; 1.0008x over previous
#include <cuda_runtime.h>

// GRU seq2seq forecaster — persistent fp32 kernel, 8 threads per batch row.
// B=4096, T_IN=168, C=32, H=64, T_OUT=24.

#define B_    4096
#define TIN   168
#define C_    32
#define H_    64
#define TOUT  24
#define RPC   28              // rows per CTA
#define TPC   (RPC * 8)       // 224 threads
#define NCTA  ((B_ + RPC - 1) / RPC)   // 147
#define WIH_S 36              // padded stride for Wih rows (32 -> 36 floats)
#define WHH_S 68              // padded stride for Whh rows (64 -> 68 floats)

// shared layout (floats)
#define SM_FLOATS (2*(192*WIH_S + 192*WHH_S) + 8*64 + 32*WHH_S + 32 + RPC*WHH_S + RPC*WIH_S)
#define SM_BYTES  (SM_FLOATS * 4)

__device__ __forceinline__ float fsig(float a) {
    // sigmoid via fast exp: max rel err ~1e-6; saturates cleanly (exp->inf/0)
    return __fdividef(1.0f, 1.0f + __expf(-a));
}
__device__ __forceinline__ float ftanh(float a) {
    // tanh(a) = 1 - 2/(exp(2a)+1); saturates cleanly for |a| large
    float e = __expf(2.0f * a);
    return 1.0f - __fdividef(2.0f, e + 1.0f);
}

// One GRU step for this thread's 8 hidden units. xv/hv are register copies of
// the full input (32) and hidden (64) vectors for this row. Writes new h
// values into sHrow[j] (4B scattered, disjoint across the row's 8 threads).
__device__ __forceinline__ void gru_step(
    const float* __restrict__ sWih, const float* __restrict__ sWhh,
    const float* __restrict__ sbr,  const float* __restrict__ sbz,
    const float* __restrict__ sbni, const float* __restrict__ sbnh,
    const float xv[C_], const float hv[H_], float* __restrict__ sHrow, int js)
{
#pragma unroll 1
    for (int i = 0; i < 8; i++) {
        const int j = js + 8 * i;          // interleaved ownership -> conflict-free LDS
        float ar  = sbr[j];                // r gate pre-act (bih_r + bhh_r folded)
        float az  = sbz[j];                // z gate pre-act
        float ani = sbni[j];               // n gate, input part (bih_n)
        float ahn = sbnh[j];               // n gate, hidden part (bhh_n)

        const float4* wr = reinterpret_cast<const float4*>(sWih + (size_t)(      j) * WIH_S);
        const float4* wz = reinterpret_cast<const float4*>(sWih + (size_t)( 64 + j) * WIH_S);
        const float4* wn = reinterpret_cast<const float4*>(sWih + (size_t)(128 + j) * WIH_S);
#pragma unroll
        for (int q = 0; q < C_ / 4; q++) {
            float4 a = wr[q], b = wz[q], c = wn[q];
            ar  = fmaf(a.x, xv[4*q+0], ar);  ar  = fmaf(a.y, xv[4*q+1], ar);
            ar  = fmaf(a.z, xv[4*q+2], ar);  ar  = fmaf(a.w, xv[4*q+3], ar);
            az  = fmaf(b.x, xv[4*q+0], az);  az  = fmaf(b.y, xv[4*q+1], az);
            az  = fmaf(b.z, xv[4*q+2], az);  az  = fmaf(b.w, xv[4*q+3], az);
            ani = fmaf(c.x, xv[4*q+0], ani); ani = fmaf(c.y, xv[4*q+1], ani);
            ani = fmaf(c.z, xv[4*q+2], ani); ani = fmaf(c.w, xv[4*q+3], ani);
        }
        const float4* ur = reinterpret_cast<const float4*>(sWhh + (size_t)(      j) * WHH_S);
        const float4* uz = reinterpret_cast<const float4*>(sWhh + (size_t)( 64 + j) * WHH_S);
        const float4* un = reinterpret_cast<const float4*>(sWhh + (size_t)(128 + j) * WHH_S);
#pragma unroll
        for (int q = 0; q < H_ / 4; q++) {
            float4 a = ur[q], b = uz[q], c = un[q];
            ar  = fmaf(a.x, hv[4*q+0], ar);  ar  = fmaf(a.y, hv[4*q+1], ar);
            ar  = fmaf(a.z, hv[4*q+2], ar);  ar  = fmaf(a.w, hv[4*q+3], ar);
            az  = fmaf(b.x, hv[4*q+0], az);  az  = fmaf(b.y, hv[4*q+1], az);
            az  = fmaf(b.z, hv[4*q+2], az);  az  = fmaf(b.w, hv[4*q+3], az);
            ahn = fmaf(c.x, hv[4*q+0], ahn); ahn = fmaf(c.y, hv[4*q+1], ahn);
            ahn = fmaf(c.z, hv[4*q+2], ahn); ahn = fmaf(c.w, hv[4*q+3], ahn);
        }
        const float r = fsig(ar);
        const float z = fsig(az);
        const float n = ftanh(fmaf(r, ahn, ani));
        const float hold = sHrow[j];       // old h_j still in shared (we only overwrite own j)
        sHrow[j] = (1.0f - z) * n + z * hold;
    }
}

__global__ __launch_bounds__(TPC, 1)
void gru_forecast_kernel(
    const float* __restrict__ x,
    const float* __restrict__ eWih, const float* __restrict__ eWhh,
    const float* __restrict__ eBih, const float* __restrict__ eBhh,
    const float* __restrict__ dWih, const float* __restrict__ dWhh,
    const float* __restrict__ dBih, const float* __restrict__ dBhh,
    const float* __restrict__ pW,   const float* __restrict__ pB,
    float* __restrict__ out)
{
    extern __shared__ float sm[];
    float* sWih_e = sm;
    float* sWhh_e = sWih_e + 192 * WIH_S;
    float* sWih_d = sWhh_e + 192 * WHH_S;
    float* sWhh_d = sWih_d + 192 * WIH_S;
    float* sbr_e  = sWhh_d + 192 * WHH_S;
    float* sbz_e  = sbr_e  + 64;
    float* sbni_e = sbz_e  + 64;
    float* sbnh_e = sbni_e + 64;
    float* sbr_d  = sbnh_e + 64;
    float* sbz_d  = sbr_d  + 64;
    float* sbni_d = sbz_d  + 64;
    float* sbnh_d = sbni_d + 64;
    float* sPW    = sbnh_d + 64;          // 32 * WHH_S
    float* sPb    = sPW   + 32 * WHH_S;   // 32
    float* sH     = sPb   + 32;           // RPC * WHH_S
    float* sPrev  = sH    + RPC * WHH_S;  // RPC * WIH_S

    const int tid = threadIdx.x;

    // ---- stage weights into padded shared (bank-phase friendly strides) ----
    for (int i = tid; i < 192 * 32; i += TPC) {
        const int j = i >> 5, k = i & 31;
        sWih_e[j * WIH_S + k] = eWih[i];
        sWih_d[j * WIH_S + k] = dWih[i];
    }
    for (int i = tid; i < 192 * 64; i += TPC) {
        const int j = i >> 6, k = i & 63;
        sWhh_e[j * WHH_S + k] = eWhh[i];
        sWhh_d[j * WHH_S + k] = dWhh[i];
    }
    for (int j = tid; j < 64; j += TPC) {
        sbr_e[j]  = eBih[j]       + eBhh[j];        // r-gate biases fold
        sbz_e[j]  = eBih[64 + j]  + eBhh[64 + j];   // z-gate biases fold
        sbni_e[j] = eBih[128 + j];
        sbnh_e[j] = eBhh[128 + j];                  // stays inside r*(...) term
        sbr_d[j]  = dBih[j]       + dBhh[j];
        sbz_d[j]  = dBih[64 + j]  + dBhh[64 + j];
        sbni_d[j] = dBih[128 + j];
        sbnh_d[j] = dBhh[128 + j];
    }
    for (int i = tid; i < 32 * 64; i += TPC) {
        const int c = i >> 6, k = i & 63;
        sPW[c * WHH_S + k] = pW[i];
    }
    for (int i = tid; i < 32; i += TPC) sPb[i] = pB[i];
    for (int i = tid; i < RPC * WHH_S; i += TPC) sH[i] = 0.0f;
    __syncthreads();   // only block barrier in the whole kernel

    const int rl = tid >> 3;       // local row 0..27
    const int js = tid & 7;        // j-slot 0..7 within row
    const int growr = blockIdx.x * RPC + rl;
    const bool active = (growr < B_);
    const int row = active ? growr : (B_ - 1);   // clamp; compute is harmless, stores guarded

    const float* xrow = x + (size_t)row * (TIN * C_);
    float* sHrow    = sH    + rl * WHH_S;
    float* sPrevRow = sPrev + rl * WIH_S;

    float hv[H_];
#pragma unroll
    for (int k = 0; k < H_; k++) hv[k] = 0.0f;
    float xv[C_];

    // ---------------- encoder: 168 steps ----------------
    for (int t = 0; t < TIN; t++) {
        const float4* xp = reinterpret_cast<const float4*>(xrow + t * C_);
#pragma unroll
        for (int q = 0; q < C_ / 4; q++) {
            float4 v = xp[q];
            xv[4*q+0] = v.x; xv[4*q+1] = v.y; xv[4*q+2] = v.z; xv[4*q+3] = v.w;
        }
        gru_step(sWih_e, sWhh_e, sbr_e, sbz_e, sbni_e, sbnh_e, xv, hv, sHrow, js);
        __syncwarp();                      // writes to sH visible to row's lanes
#pragma unroll
        for (int q = 0; q < H_ / 4; q++) { // reload full h into registers
            float4 v = *reinterpret_cast<const float4*>(sHrow + 4 * q);
            hv[4*q+0] = v.x; hv[4*q+1] = v.y; hv[4*q+2] = v.z; hv[4*q+3] = v.w;
        }
        __syncwarp();                      // all lanes done reading before next writes
    }

    // decoder start token: prev = x[:, T_IN-1, :]
    {
        const float4* xp = reinterpret_cast<const float4*>(xrow + (TIN - 1) * C_);
        float4 v = xp[js];
        *reinterpret_cast<float4*>(sPrevRow + 4 * js) = v;
        __syncwarp();
    }

    // ---------------- decoder: 24 steps ----------------
    const int c0 = 4 * js;   // this thread's 4 projection outputs
    for (int t = 0; t < TOUT; t++) {
#pragma unroll
        for (int q = 0; q < C_ / 4; q++) {
            float4 v = *reinterpret_cast<const float4*>(sPrevRow + 4 * q);
            xv[4*q+0] = v.x; xv[4*q+1] = v.y; xv[4*q+2] = v.z; xv[4*q+3] = v.w;
        }
        __syncwarp();                      // prev reads done before anyone rewrites sPrev
        gru_step(sWih_d, sWhh_d, sbr_d, sbz_d, sbni_d, sbnh_d, xv, hv, sHrow, js);
        __syncwarp();
#pragma unroll
        for (int q = 0; q < H_ / 4; q++) {
            float4 v = *reinterpret_cast<const float4*>(sHrow + 4 * q);
            hv[4*q+0] = v.x; hv[4*q+1] = v.y; hv[4*q+2] = v.z; hv[4*q+3] = v.w;
        }
        // projection: pred[c0..c0+3] = h @ proj_W^T + b
        float p0 = sPb[c0 + 0], p1 = sPb[c0 + 1], p2 = sPb[c0 + 2], p3 = sPb[c0 + 3];
        const float4* w0 = reinterpret_cast<const float4*>(sPW + (size_t)(c0 + 0) * WHH_S);
        const float4* w1 = reinterpret_cast<const float4*>(sPW + (size_t)(c0 + 1) * WHH_S);
        const float4* w2 = reinterpret_cast<const float4*>(sPW + (size_t)(c0 + 2) * WHH_S);
        const float4* w3 = reinterpret_cast<const float4*>(sPW + (size_t)(c0 + 3) * WHH_S);
#pragma unroll
        for (int q = 0; q < H_ / 4; q++) {
            float4 a = w0[q], b = w1[q], c = w2[q], d = w3[q];
            p0 = fmaf(a.x, hv[4*q+0], p0); p0 = fmaf(a.y, hv[4*q+1], p0);
            p0 = fmaf(a.z, hv[4*q+2], p0); p0 = fmaf(a.w, hv[4*q+3], p0);
            p1 = fmaf(b.x, hv[4*q+0], p1); p1 = fmaf(b.y, hv[4*q+1], p1);
            p1 = fmaf(b.z, hv[4*q+2], p1); p1 = fmaf(b.w, hv[4*q+3], p1);
            p2 = fmaf(c.x, hv[4*q+0], p2); p2 = fmaf(c.y, hv[4*q+1], p2);
            p2 = fmaf(c.z, hv[4*q+2], p2); p2 = fmaf(c.w, hv[4*q+3], p2);
            p3 = fmaf(d.x, hv[4*q+0], p3); p3 = fmaf(d.y, hv[4*q+1], p3);
            p3 = fmaf(d.z, hv[4*q+2], p3); p3 = fmaf(d.w, hv[4*q+3], p3);
        }
        float4 pr = make_float4(p0, p1, p2, p3);
        *reinterpret_cast<float4*>(sPrevRow + c0) = pr;   // becomes next step's input
        if (active) {
            *reinterpret_cast<float4*>(out + ((size_t)row * TOUT + t) * C_ + c0) = pr;
        }
        __syncwarp();
    }
}

extern "C" void kernel_launch(void* const* d_in, const int* in_sizes, int n_in,
                              void* d_out, int out_size)
{
    (void)in_sizes; (void)n_in; (void)out_size;
    const float* x    = (const float*)d_in[0];
    const float* eWih = (const float*)d_in[1];
    const float* eWhh = (const float*)d_in[2];
    const float* eBih = (const float*)d_in[3];
    const float* eBhh = (const float*)d_in[4];
    const float* dWih = (const float*)d_in[5];
    const float* dWhh = (const float*)d_in[6];
    const float* dBih = (const float*)d_in[7];
    const float* dBhh = (const float*)d_in[8];
    const float* pW   = (const float*)d_in[9];
    const float* pB   = (const float*)d_in[10];
    float* out = (float*)d_out;

    cudaFuncSetAttribute(gru_forecast_kernel,
                         cudaFuncAttributeMaxDynamicSharedMemorySize, SM_BYTES);
    gru_forecast_kernel<<<NCTA, TPC, SM_BYTES>>>(
        x, eWih, eWhh, eBih, eBhh, dWih, dWhh, dBih, dBhh, pW, pB, out);
}

// round 4
// speedup vs baseline: 1.6902x; 1.6889x over previous
#include <cuda_runtime.h>

// GRU seq2seq forecaster, two-kernel design:
//  K1: gi[t,b,192] = x[b,t,:] @ enc_Wih^T + bih (+bhh for r,z gates)  (parallel)
//  K2: persistent recurrence. thread = hidden unit, Whh rows in REGISTERS,
//      h broadcast from double-buffered SMEM, gi streamed from DRAM scratch.

#define B_    4096
#define TIN   168
#define C_    32
#define H_    64
#define TOUT  24
#define G3    192

// 528 MB scratch for encoder input-gate preactivations, layout [(t*4096+b)*192 + o]
__device__ float g_gi[(size_t)TIN * B_ * G3];

__device__ __forceinline__ float fsig(float a) {
    return __fdividef(1.0f, 1.0f + __expf(-a));
}
__device__ __forceinline__ float ftanh(float a) {
    float e = __expf(2.0f * a);
    return 1.0f - __fdividef(2.0f, e + 1.0f);
}

#define FMA4(acc, w4, h4) \
    acc = fmaf((w4).x, (h4).x, acc); acc = fmaf((w4).y, (h4).y, acc); \
    acc = fmaf((w4).z, (h4).z, acc); acc = fmaf((w4).w, (h4).w, acc);

// ============================ kernel 1: gi precompute ============================
#define K1_TH 192
#define K1_P  16
#define K1_GRID 1184

__global__ __launch_bounds__(K1_TH)
void gi_kernel(const float* __restrict__ x, const float* __restrict__ eWih,
               const float* __restrict__ eBih, const float* __restrict__ eBhh)
{
    __shared__ float sX[K1_P * C_];
    const int o = threadIdx.x;                 // output gate-row 0..191 (weights in regs)
    float4 w[8];
#pragma unroll
    for (int q = 0; q < 8; q++) w[q] = reinterpret_cast<const float4*>(eWih)[o * 8 + q];
    const float bo = eBih[o] + ((o < 2 * H_) ? eBhh[o] : 0.0f);   // fold bhh for r,z

    const int nIter = (TIN * B_) / K1_P;
    for (int it = blockIdx.x; it < nIter; it += gridDim.x) {
        const int P = it * K1_P;
        __syncthreads();                       // previous iter's readers done with sX
        for (int idx = o; idx < K1_P * C_; idx += K1_TH) {
            const int pl = idx >> 5, c = idx & 31;
            const int p = P + pl;
            const int b = p & (B_ - 1), t = p >> 12;
            sX[idx] = x[((size_t)b * TIN + t) * C_ + c];
        }
        __syncthreads();
#pragma unroll
        for (int pl = 0; pl < K1_P; pl++) {
            const float4* xr = reinterpret_cast<const float4*>(sX + pl * C_);  // broadcast
            float acc = bo;
#pragma unroll
            for (int q = 0; q < 8; q++) { const float4 v = xr[q]; FMA4(acc, w[q], v); }
            g_gi[(size_t)(P + pl) * G3 + o] = acc;   // lanes consecutive o -> coalesced
        }
    }
}

// ============================ kernel 2: recurrence ============================
#define NG    4                 // groups per CTA
#define CTA2  256               // 4 groups x 64 threads
#define GRID2 148
#define RPG   7                 // rows per group: 148*4*7 = 4144 >= 4096 (clamped dups benign)
#define DW_S  33                // dec Wih smem stride (conflict-free LDS.32)
#define PW_S  68                // proj W smem stride (16B-aligned float4)

// shared layout (float offsets)
#define SH_HBUF 0
#define HBUF_SZ (2 * NG * RPG * 64)           // 3584
#define SH_PREV (SH_HBUF + HBUF_SZ)
#define PREV_SZ (2 * NG * RPG * 32)           // 1792
#define SH_DWIH (SH_PREV + PREV_SZ)
#define DWIH_SZ (G3 * DW_S)                   // 6336
#define SH_PW   (SH_DWIH + DWIH_SZ)
#define PW_SZ   (C_ * PW_S)                   // 2176
#define SH_DB   (SH_PW + PW_SZ)
#define DB_SZ   (4 * 64 + 32)                 // dbr,dbz,dbni,dbnh,pb
#define SM2_FLOATS (SH_DB + DB_SZ)
#define SM2_BYTES  (SM2_FLOATS * 4)

__global__ __launch_bounds__(CTA2, 1)
void gru_rec_kernel(const float* __restrict__ x,
                    const float* __restrict__ eWhh, const float* __restrict__ eBhh,
                    const float* __restrict__ dWih, const float* __restrict__ dWhh,
                    const float* __restrict__ dBih, const float* __restrict__ dBhh,
                    const float* __restrict__ pW,   const float* __restrict__ pB,
                    float* __restrict__ out)
{
    extern __shared__ float sm[];
    const int tid = threadIdx.x;
    const int g = tid >> 6;        // group 0..3
    const int u = tid & 63;        // hidden unit

    // ---- stage decoder-side constants into shared ----
    for (int i = tid; i < G3 * C_; i += CTA2)
        sm[SH_DWIH + (i >> 5) * DW_S + (i & 31)] = dWih[i];
    for (int i = tid; i < C_ * H_; i += CTA2)
        sm[SH_PW + (i >> 6) * PW_S + (i & 63)] = pW[i];
    if (tid < 64) {
        sm[SH_DB + tid]       = dBih[tid]      + dBhh[tid];        // r
        sm[SH_DB + 64 + tid]  = dBih[64 + tid] + dBhh[64 + tid];   // z
        sm[SH_DB + 128 + tid] = dBih[128 + tid];                   // n (input part)
        sm[SH_DB + 192 + tid] = dBhh[128 + tid];                   // n (hidden part)
    }
    if (tid < 32) sm[SH_DB + 256 + tid] = pB[tid];

    float* hbufG = sm + SH_HBUF + g * (RPG * 64);
    float* prevG = sm + SH_PREV + g * (RPG * 32);
    const int HP = NG * RPG * 64;     // hbuf parity stride
    const int PP = NG * RPG * 32;     // prev parity stride
#pragma unroll
    for (int i = 0; i < RPG; i++) hbufG[i * 64 + u] = 0.0f;   // h0 = 0 in parity 0

    // ---- encoder Whh rows for this unit -> registers (192 floats) ----
    float4 wr[16], wz[16], wn[16];
#pragma unroll
    for (int q = 0; q < 16; q++) {
        wr[q] = reinterpret_cast<const float4*>(eWhh)[(      u) * 16 + q];
        wz[q] = reinterpret_cast<const float4*>(eWhh)[( 64 + u) * 16 + q];
        wn[q] = reinterpret_cast<const float4*>(eWhh)[(128 + u) * 16 + q];
    }
    float bhn = eBhh[128 + u];

    __syncthreads();

    const int rowbase = (blockIdx.x * NG + g) * RPG;
    int par = 0;

    // ======================= encoder: 168 steps =======================
    for (int t = 0; t < TIN; t++) {
        const float* gsrc = g_gi + (size_t)t * (B_ * G3) + u;
        const float* hR = hbufG + par * HP;
        float* hW = hbufG + (par ^ 1) * HP;

        // software pipeline: preload pair 0's gi
        int r0 = min(rowbase + 0, B_ - 1) * G3;
        int r1 = min(rowbase + 1, B_ - 1) * G3;
        float grA = gsrc[r0], gzA = gsrc[r0 + 64], gnA = gsrc[r0 + 128];
        float grB = gsrc[r1], gzB = gsrc[r1 + 64], gnB = gsrc[r1 + 128];

#pragma unroll 1
        for (int pi = 0; pi < RPG - 1; pi += 2) {
            // prefetch next pair's gi (rows pi+2, pi+3; clamped reads are harmless)
            const int rC = min(rowbase + pi + 2, B_ - 1) * G3;
            const int rD = min(rowbase + pi + 3, B_ - 1) * G3;
            const float grC = gsrc[rC], gzC = gsrc[rC + 64], gnC = gsrc[rC + 128];
            const float grD = gsrc[rD], gzD = gsrc[rD + 64], gnD = gsrc[rD + 128];

            const float4* hA = reinterpret_cast<const float4*>(hR + pi * 64);
            const float4* hB = reinterpret_cast<const float4*>(hR + (pi + 1) * 64);
            float arA = 0.f, azA = 0.f, ahA = 0.f;
            float arB = 0.f, azB = 0.f, ahB = 0.f;
#pragma unroll
            for (int q = 0; q < 16; q++) {
                const float4 a = hA[q], b = hB[q];   // broadcast LDS (N=1)
                FMA4(arA, wr[q], a); FMA4(azA, wz[q], a); FMA4(ahA, wn[q], a);
                FMA4(arB, wr[q], b); FMA4(azB, wz[q], b); FMA4(ahB, wn[q], b);
            }
            const float holdA = hR[pi * 64 + u];
            const float holdB = hR[(pi + 1) * 64 + u];
            const float rgA = fsig(arA + grA), zgA = fsig(azA + gzA);
            const float nA  = ftanh(fmaf(rgA, ahA + bhn, gnA));
            const float hnA = (1.0f - zgA) * nA + zgA * holdA;
            const float rgB = fsig(arB + grB), zgB = fsig(azB + gzB);
            const float nB  = ftanh(fmaf(rgB, ahB + bhn, gnB));
            const float hnB = (1.0f - zgB) * nB + zgB * holdB;
            hW[pi * 64 + u] = hnA;
            hW[(pi + 1) * 64 + u] = hnB;

            grA = grC; gzA = gzC; gnA = gnC;
            grB = grD; gzB = gzD; gnB = gnD;
        }
        { // last (odd) row i=6 — its gi already prefetched into A regs
            const int i6 = RPG - 1;
            const float4* hA = reinterpret_cast<const float4*>(hR + i6 * 64);
            float arA = 0.f, azA = 0.f, ahA = 0.f;
#pragma unroll
            for (int q = 0; q < 16; q++) {
                const float4 a = hA[q];
                FMA4(arA, wr[q], a); FMA4(azA, wz[q], a); FMA4(ahA, wn[q], a);
            }
            const float holdA = hR[i6 * 64 + u];
            const float rgA = fsig(arA + grA), zgA = fsig(azA + gzA);
            const float nA  = ftanh(fmaf(rgA, ahA + bhn, gnA));
            hW[i6 * 64 + u] = (1.0f - zgA) * nA + zgA * holdA;
        }
        asm volatile("bar.sync %0, %1;" :: "r"(g), "r"(64) : "memory");
        par ^= 1;
    }
    // par == 0 here; final h lives in hbuf parity 0.

    // ======================= decoder: 24 steps =======================
    // reload this unit's DECODER Whh rows into the same registers
#pragma unroll
    for (int q = 0; q < 16; q++) {
        wr[q] = reinterpret_cast<const float4*>(dWhh)[(      u) * 16 + q];
        wz[q] = reinterpret_cast<const float4*>(dWhh)[( 64 + u) * 16 + q];
        wn[q] = reinterpret_cast<const float4*>(dWhh)[(128 + u) * 16 + q];
    }
    const float dbr  = sm[SH_DB + u],        dbz  = sm[SH_DB + 64 + u];
    const float dbni = sm[SH_DB + 128 + u],  dbnh = sm[SH_DB + 192 + u];

    // prev_0 = x[:, TIN-1, :]
    if (u < 32) {
#pragma unroll 1
        for (int i = 0; i < RPG; i++) {
            const int r = min(rowbase + i, B_ - 1);
            prevG[i * 32 + u] = x[((size_t)r * TIN + (TIN - 1)) * C_ + u];
        }
    }
    asm volatile("bar.sync %0, %1;" :: "r"(g), "r"(64) : "memory");

    int ppar = 0;
    for (int t = 0; t < TOUT; t++) {
        const float* hR = hbufG + par * HP;
        float* hW = hbufG + (par ^ 1) * HP;
        const float* pv = prevG + ppar * PP;
        float* pvN = prevG + (ppar ^ 1) * PP;

#pragma unroll 1
        for (int i = 0; i < RPG; i++) {
            float ar = dbr, az = dbz, ani = dbni, ah = dbnh;
            const float4* p4p = reinterpret_cast<const float4*>(pv + i * 32); // broadcast
#pragma unroll
            for (int q = 0; q < 8; q++) {
                const float4 p4 = p4p[q];
                const float* wir = sm + SH_DWIH + (      u) * DW_S + 4 * q;
                const float* wiz = sm + SH_DWIH + ( 64 + u) * DW_S + 4 * q;
                const float* win = sm + SH_DWIH + (128 + u) * DW_S + 4 * q;
                ar  = fmaf(wir[0], p4.x, ar);  ar  = fmaf(wir[1], p4.y, ar);
                ar  = fmaf(wir[2], p4.z, ar);  ar  = fmaf(wir[3], p4.w, ar);
                az  = fmaf(wiz[0], p4.x, az);  az  = fmaf(wiz[1], p4.y, az);
                az  = fmaf(wiz[2], p4.z, az);  az  = fmaf(wiz[3], p4.w, az);
                ani = fmaf(win[0], p4.x, ani); ani = fmaf(win[1], p4.y, ani);
                ani = fmaf(win[2], p4.z, ani); ani = fmaf(win[3], p4.w, ani);
            }
            const float4* hA = reinterpret_cast<const float4*>(hR + i * 64);
#pragma unroll
            for (int q = 0; q < 16; q++) {
                const float4 a = hA[q];
                FMA4(ar, wr[q], a); FMA4(az, wz[q], a); FMA4(ah, wn[q], a);
            }
            const float rg = fsig(ar), zg = fsig(az);
            const float nn = ftanh(fmaf(rg, ah, ani));
            const float hold = hR[i * 64 + u];
            hW[i * 64 + u] = (1.0f - zg) * nn + zg * hold;
        }
        asm volatile("bar.sync %0, %1;" :: "r"(g), "r"(64) : "memory");

        // projection + next decoder input (threads u<32: one output channel each)
        if (u < 32) {
#pragma unroll 1
            for (int i = 0; i < RPG; i++) {
                const float4* h4 = reinterpret_cast<const float4*>(hW + i * 64);
                float p = sm[SH_DB + 256 + u];
#pragma unroll
                for (int q = 0; q < 16; q++) {
                    const float4 hh = h4[q];
                    const float4 w4 = *reinterpret_cast<const float4*>(sm + SH_PW + u * PW_S + 4 * q);
                    FMA4(p, w4, hh);
                }
                pvN[i * 32 + u] = p;
                const int r = min(rowbase + i, B_ - 1);
                out[((size_t)r * TOUT + t) * C_ + u] = p;
            }
        }
        asm volatile("bar.sync %0, %1;" :: "r"(g), "r"(64) : "memory");
        par ^= 1; ppar ^= 1;
    }
}

// ============================ launch ============================
extern "C" void kernel_launch(void* const* d_in, const int* in_sizes, int n_in,
                              void* d_out, int out_size)
{
    (void)in_sizes; (void)n_in; (void)out_size;
    const float* x    = (const float*)d_in[0];
    const float* eWih = (const float*)d_in[1];
    const float* eWhh = (const float*)d_in[2];
    const float* eBih = (const float*)d_in[3];
    const float* eBhh = (const float*)d_in[4];
    const float* dWih = (const float*)d_in[5];
    const float* dWhh = (const float*)d_in[6];
    const float* dBih = (const float*)d_in[7];
    const float* dBhh = (const float*)d_in[8];
    const float* pW   = (const float*)d_in[9];
    const float* pB   = (const float*)d_in[10];
    float* out = (float*)d_out;

    gi_kernel<<<K1_GRID, K1_TH>>>(x, eWih, eBih, eBhh);

    cudaFuncSetAttribute(gru_rec_kernel,
                         cudaFuncAttributeMaxDynamicSharedMemorySize, SM2_BYTES);
    gru_rec_kernel<<<GRID2, CTA2, SM2_BYTES>>>(
        x, eWhh, eBhh, dWih, dWhh, dBih, dBhh, pW, pB, out);
}